// round 1
// baseline (speedup 1.0000x reference)
#include <cuda_runtime.h>
#include <cuda_bf16.h>
#include <cstdint>

// Problem constants
#define BATCH 32
#define NN    1024
#define NDIM  14
#define HID   64
#define HEAD  128
#define MAXD  64          // max neighbors kept per row (mean ~11.2, P(>64) ~ 0)

#define TOTAL_NODES (BATCH * NN)   // 32768

// ---------------- device scratch (alloc-free rule: static globals) -----------
__device__ int   g_nbr[TOTAL_NODES * MAXD];   // neighbor column indices (8 MB)
__device__ int   g_cnt[TOTAL_NODES];          // clamped neighbor counts
__device__ float g_dinv[TOTAL_NODES];         // deg^-1/2
__device__ float g_h1[TOTAL_NODES * HID];     // layer activations (8 MB)
__device__ float g_h2[TOTAL_NODES * HID];     // layer activations (8 MB)

// ---------------- 1) adjacency scan -> CSR-ish neighbor lists ----------------
// One warp per adjacency row. Deterministic (ballot + prefix popc, column order).
__global__ void build_edges_kernel(const float* __restrict__ adj) {
    int row  = blockIdx.x * 8 + (threadIdx.x >> 5);   // 8 warps / block
    int lane = threadIdx.x & 31;
    if (row >= TOTAL_NODES) return;

    const float* arow = adj + (size_t)row * NN;
    int* nl = &g_nbr[(size_t)row * MAXD];
    int cnt = 0;

    #pragma unroll 4
    for (int s = 0; s < NN / 32; s++) {
        float v = arow[s * 32 + lane];
        unsigned m = __ballot_sync(0xffffffffu, v > 0.5f);
        if (v > 0.5f) {
            int pos = cnt + __popc(m & ((1u << lane) - 1u));
            if (pos < MAXD) nl[pos] = s * 32 + lane;
        }
        cnt += __popc(m);
    }
    if (lane == 0) {
        g_cnt[row]  = cnt < MAXD ? cnt : MAXD;
        g_dinv[row] = rsqrtf((float)cnt);   // cnt >= 1 (self-loop), clip(deg,1) implicit
    }
}

// ---------------- 2) fused sparse-gather + GEMM + bias + ReLU ----------------
// Computes: out = relu( (D^-1/2 A D^-1/2 @ in) @ W + b ), one layer.
// Block: 64 nodes (same batch since N % 64 == 0), 256 threads.
// Phase A: 4 threads/node gather DIN dims into shared (k-major).
// Phase B: 16x16 threads, 4x4 register microtile GEMM from shared.
template <int DIN>
__global__ void gcn_layer_kernel(const float* __restrict__ in,
                                 const float* __restrict__ W,
                                 const float* __restrict__ bias,
                                 float* __restrict__ out) {
    __shared__ float As[DIN][68];      // k-major gathered tile, padded, 16B-aligned rows
    __shared__ float Ws[DIN][64];      // W (k-major, matches row-major [DIN,64])
    __shared__ float bs[64];

    const int tid       = threadIdx.x;
    const int blockBase = blockIdx.x * 64;       // first global node of this block
    const int bbase     = blockBase & ~(NN - 1); // batch start (N=1024 divides 64-groups)

    // cooperative loads of W, b
    for (int i = tid; i < DIN * 64; i += 256) Ws[i >> 6][i & 63] = W[i];
    if (tid < 64) bs[tid] = bias[tid];

    // ---- Phase A: gather ----
    {
        const int n  = tid >> 2;                 // node within block (0..63)
        const int kq = tid & 3;                  // quarter of the k-range
        const int node = blockBase + n;
        constexpr int KPT = (DIN + 3) / 4;       // k's per thread (16 for 64, 4 for 14->16)

        float acc[KPT];
        #pragma unroll
        for (int q = 0; q < KPT; q++) acc[q] = 0.0f;

        const int cnt = g_cnt[node];
        const int* nl = &g_nbr[(size_t)node * MAXD];

        for (int j = 0; j < cnt; j++) {
            const int jj = nl[j];
            const float dj = g_dinv[bbase + jj];
            const float* hp = in + (size_t)(bbase + jj) * DIN + kq * KPT;
            #pragma unroll
            for (int q = 0; q < KPT; q++) {
                if ((DIN & 3) == 0) {
                    acc[q] += dj * hp[q];
                } else {
                    if (kq * KPT + q < DIN) acc[q] += dj * hp[q];
                }
            }
        }
        const float di = g_dinv[node];
        #pragma unroll
        for (int q = 0; q < KPT; q++) {
            const int k = kq * KPT + q;
            if (k < DIN) As[k][n] = di * acc[q];
        }
    }
    __syncthreads();

    // ---- Phase B: GEMM [64 nodes x DIN] @ [DIN x 64] ----
    {
        const int tx = tid & 15;   // output-column group (4 cols)
        const int ty = tid >> 4;   // node-row group (4 rows)
        float c[4][4];
        #pragma unroll
        for (int i = 0; i < 4; i++)
            #pragma unroll
            for (int j = 0; j < 4; j++) c[i][j] = 0.0f;

        #pragma unroll
        for (int k = 0; k < DIN; k++) {
            const float4 av = *(const float4*)&As[k][ty * 4];
            const float4 bv = *(const float4*)&Ws[k][tx * 4];
            const float a[4] = {av.x, av.y, av.z, av.w};
            const float bb[4] = {bv.x, bv.y, bv.z, bv.w};
            #pragma unroll
            for (int i = 0; i < 4; i++)
                #pragma unroll
                for (int j = 0; j < 4; j++) c[i][j] = fmaf(a[i], bb[j], c[i][j]);
        }

        #pragma unroll
        for (int i = 0; i < 4; i++) {
            const int row = blockBase + ty * 4 + i;
            float4 o;
            o.x = fmaxf(c[i][0] + bs[tx * 4 + 0], 0.0f);
            o.y = fmaxf(c[i][1] + bs[tx * 4 + 1], 0.0f);
            o.z = fmaxf(c[i][2] + bs[tx * 4 + 2], 0.0f);
            o.w = fmaxf(c[i][3] + bs[tx * 4 + 3], 0.0f);
            *(float4*)&out[(size_t)row * 64 + tx * 4] = o;
        }
    }
}

// ---------------- 3) mean-pool + 2-layer MLP head ----------------------------
// One block per batch element, 128 threads.
__global__ void head_kernel(const float* __restrict__ h,
                            const float* __restrict__ Wf1,
                            const float* __restrict__ bf1,
                            const float* __restrict__ Wf2,
                            const float* __restrict__ bf2,
                            float* __restrict__ out) {
    const int b   = blockIdx.x;
    const int tid = threadIdx.x;
    __shared__ float pooled[64];
    __shared__ float red[128];

    // mean over N of h[b, :, k]
    const int k    = tid & 63;
    const int half = tid >> 6;
    const float* hb = h + (size_t)b * NN * HID;
    float s = 0.0f;
    #pragma unroll 8
    for (int i = 0; i < NN / 2; i++) s += hb[(size_t)(half * (NN / 2) + i) * HID + k];
    red[tid] = s;
    __syncthreads();
    if (tid < 64) pooled[tid] = (red[tid] + red[tid + 64]) * (1.0f / (float)NN);
    __syncthreads();

    // f1 = relu(pooled @ Wf1 + bf1); contribution f1[t] * Wf2[t]
    float a = bf1[tid];
    #pragma unroll
    for (int kk = 0; kk < 64; kk++) a = fmaf(pooled[kk], Wf1[kk * HEAD + tid], a);
    float f = fmaxf(a, 0.0f) * Wf2[tid];

    red[tid] = f;
    __syncthreads();
    for (int off = 64; off > 0; off >>= 1) {
        if (tid < off) red[tid] += red[tid + off];
        __syncthreads();
    }
    if (tid == 0) out[b] = red[0] + bf2[0];
}

// ---------------- launch ------------------------------------------------------
extern "C" void kernel_launch(void* const* d_in, const int* in_sizes, int n_in,
                              void* d_out, int out_size) {
    const float* x   = (const float*)d_in[0];
    const float* adj = (const float*)d_in[1];
    const float* W1  = (const float*)d_in[2];
    const float* b1  = (const float*)d_in[3];
    const float* W2  = (const float*)d_in[4];
    const float* b2  = (const float*)d_in[5];
    const float* W3  = (const float*)d_in[6];
    const float* b3  = (const float*)d_in[7];
    const float* Wf1 = (const float*)d_in[8];
    const float* bf1 = (const float*)d_in[9];
    const float* Wf2 = (const float*)d_in[10];
    const float* bf2 = (const float*)d_in[11];
    float* out = (float*)d_out;

    float *h1, *h2;
    cudaGetSymbolAddress((void**)&h1, g_h1);
    cudaGetSymbolAddress((void**)&h2, g_h2);

    build_edges_kernel<<<TOTAL_NODES / 8, 256>>>(adj);
    gcn_layer_kernel<NDIM><<<TOTAL_NODES / 64, 256>>>(x,  W1, b1, h1);
    gcn_layer_kernel<HID> <<<TOTAL_NODES / 64, 256>>>(h1, W2, b2, h2);
    gcn_layer_kernel<HID> <<<TOTAL_NODES / 64, 256>>>(h2, W3, b3, h1);
    head_kernel<<<BATCH, 128>>>(h1, Wf1, bf1, Wf2, bf2, out);
}

// round 2
// speedup vs baseline: 3.1092x; 3.1092x over previous
#include <cuda_runtime.h>
#include <cuda_bf16.h>
#include <cstdint>

#define BATCH 32
#define NN    1024
#define NDIM  14
#define HID   64
#define HEAD  128
#define MAXD  64
#define TOTAL_NODES (BATCH * NN)   // 32768

// ---------------- device scratch ----------------
__device__ int   g_nbr[TOTAL_NODES * MAXD];
__device__ int   g_cnt[TOTAL_NODES];
__device__ float g_dinv[TOTAL_NODES];
__device__ float g_h1[TOTAL_NODES * HID];
__device__ float g_h2[TOTAL_NODES * HID];
__device__ float g_pool[BATCH * 16 * HID];

// ---------------- 1) adjacency scan (float4, warp per row) ----------------
__global__ void build_edges_kernel(const float* __restrict__ adj) {
    int row  = blockIdx.x * 8 + (threadIdx.x >> 5);
    int lane = threadIdx.x & 31;
    if (row >= TOTAL_NODES) return;

    const float4* arow = (const float4*)(adj + (size_t)row * NN);
    int* nl = &g_nbr[(size_t)row * MAXD];
    int cnt = 0;
    const unsigned lt = (1u << lane) - 1u;

    #pragma unroll
    for (int s = 0; s < NN / 128; s++) {           // 8 iterations
        float4 v = arow[s * 32 + lane];
        bool b0 = v.x > 0.5f, b1 = v.y > 0.5f, b2 = v.z > 0.5f, b3 = v.w > 0.5f;
        unsigned m0 = __ballot_sync(0xffffffffu, b0);
        unsigned m1 = __ballot_sync(0xffffffffu, b1);
        unsigned m2 = __ballot_sync(0xffffffffu, b2);
        unsigned m3 = __ballot_sync(0xffffffffu, b3);
        int prior = __popc(m0 & lt) + __popc(m1 & lt) + __popc(m2 & lt) + __popc(m3 & lt);
        int colbase = s * 128 + lane * 4;
        int p = cnt + prior;
        if (b0) { if (p < MAXD) nl[p] = colbase + 0; p++; }
        if (b1) { if (p < MAXD) nl[p] = colbase + 1; p++; }
        if (b2) { if (p < MAXD) nl[p] = colbase + 2; p++; }
        if (b3) { if (p < MAXD) nl[p] = colbase + 3; }
        cnt += __popc(m0) + __popc(m1) + __popc(m2) + __popc(m3);
    }
    if (lane == 0) {
        g_cnt[row]  = cnt < MAXD ? cnt : MAXD;
        g_dinv[row] = rsqrtf((float)cnt);
    }
}

// ---------------- 2) fused sparse-gather + GEMM + bias + ReLU ----------------
// out = relu( dinv_i * sum_j (in_scaled_j) @ W + b ) [* dinv_i if SCALE_OUT]
// SCALE_IN: multiply each gathered row by dinv_j (only layer 1; later layers
// consume pre-scaled activations).
template <int DIN, bool SCALE_IN, bool SCALE_OUT>
__global__ __launch_bounds__(256)
void gcn_layer_kernel(const float* __restrict__ in,
                      const float* __restrict__ W,
                      const float* __restrict__ bias,
                      float* __restrict__ out) {
    constexpr int KPAD = (DIN + 3) & ~3;
    __shared__ float Ag[64][68];          // node-major gathered tile (row 272B)
    __shared__ float Ws[KPAD][64];
    __shared__ float bs[64];

    const int tid       = threadIdx.x;
    const int blockBase = blockIdx.x * 64;
    const int bbase     = blockBase & ~(NN - 1);

    for (int i = tid; i < KPAD * 64; i += 256) {
        int r = i >> 6;
        Ws[r][i & 63] = (r < DIN) ? W[r * 64 + (i & 63)] : 0.0f;
    }
    if (tid < 64) bs[tid] = bias[tid];

    // ---- Phase A: coalesced gather, 16 threads per node ----
    const int grp  = tid >> 4;   // 0..15
    const int lane = tid & 15;   // 0..15

    #pragma unroll
    for (int s = 0; s < 4; s++) {
        const int n    = grp * 4 + s;
        const int node = blockBase + n;
        const int cnt  = g_cnt[node];
        const int* nl  = &g_nbr[(size_t)node * MAXD];

        if (DIN == 64) {
            float4 acc = make_float4(0.f, 0.f, 0.f, 0.f);
            int j = 0;
            for (; j + 2 <= cnt; j += 2) {
                const int j0 = nl[j], j1 = nl[j + 1];
                const float4 v0 = *(const float4*)(in + (size_t)(bbase + j0) * 64 + lane * 4);
                const float4 v1 = *(const float4*)(in + (size_t)(bbase + j1) * 64 + lane * 4);
                if (SCALE_IN) {
                    const float d0 = g_dinv[bbase + j0], d1 = g_dinv[bbase + j1];
                    acc.x += d0 * v0.x + d1 * v1.x;
                    acc.y += d0 * v0.y + d1 * v1.y;
                    acc.z += d0 * v0.z + d1 * v1.z;
                    acc.w += d0 * v0.w + d1 * v1.w;
                } else {
                    acc.x += v0.x + v1.x; acc.y += v0.y + v1.y;
                    acc.z += v0.z + v1.z; acc.w += v0.w + v1.w;
                }
            }
            if (j < cnt) {
                const int j0 = nl[j];
                const float4 v0 = *(const float4*)(in + (size_t)(bbase + j0) * 64 + lane * 4);
                const float d0 = SCALE_IN ? g_dinv[bbase + j0] : 1.0f;
                acc.x += d0 * v0.x; acc.y += d0 * v0.y;
                acc.z += d0 * v0.z; acc.w += d0 * v0.w;
            }
            const float di = g_dinv[node];
            acc.x *= di; acc.y *= di; acc.z *= di; acc.w *= di;
            *(float4*)&Ag[n][lane * 4] = acc;
        } else {
            // DIN=14: lanes 0..13 each own one k; lanes 14,15 pad zeros
            float acc = 0.0f;
            if (lane < DIN) {
                for (int j = 0; j < cnt; j++) {
                    const int jj = nl[j];
                    const float v = in[(size_t)(bbase + jj) * DIN + lane];
                    acc += SCALE_IN ? g_dinv[bbase + jj] * v : v;
                }
                Ag[n][lane] = g_dinv[node] * acc;
            } else if (lane < KPAD) {
                Ag[n][lane] = 0.0f;
            }
        }
    }
    __syncthreads();

    // ---- Phase B: [64 x KPAD] @ [KPAD x 64], 4x4 microtiles ----
    {
        const int tx = tid & 15;
        const int ty = tid >> 4;
        float c[4][4];
        #pragma unroll
        for (int i = 0; i < 4; i++)
            #pragma unroll
            for (int j = 0; j < 4; j++) c[i][j] = 0.0f;

        #pragma unroll
        for (int kk = 0; kk < KPAD; kk += 4) {
            float4 a[4], b[4];
            #pragma unroll
            for (int i = 0; i < 4; i++) a[i] = *(const float4*)&Ag[ty * 4 + i][kk];
            #pragma unroll
            for (int q = 0; q < 4; q++) b[q] = *(const float4*)&Ws[kk + q][tx * 4];
            #pragma unroll
            for (int i = 0; i < 4; i++) {
                const float ai[4] = {a[i].x, a[i].y, a[i].z, a[i].w};
                #pragma unroll
                for (int q = 0; q < 4; q++) {
                    c[i][0] = fmaf(ai[q], b[q].x, c[i][0]);
                    c[i][1] = fmaf(ai[q], b[q].y, c[i][1]);
                    c[i][2] = fmaf(ai[q], b[q].z, c[i][2]);
                    c[i][3] = fmaf(ai[q], b[q].w, c[i][3]);
                }
            }
        }

        #pragma unroll
        for (int i = 0; i < 4; i++) {
            const int row = blockBase + ty * 4 + i;
            const float dscale = SCALE_OUT ? g_dinv[row] : 1.0f;
            float4 o;
            o.x = fmaxf(c[i][0] + bs[tx * 4 + 0], 0.0f) * dscale;
            o.y = fmaxf(c[i][1] + bs[tx * 4 + 1], 0.0f) * dscale;
            o.z = fmaxf(c[i][2] + bs[tx * 4 + 2], 0.0f) * dscale;
            o.w = fmaxf(c[i][3] + bs[tx * 4 + 3], 0.0f) * dscale;
            *(float4*)&out[(size_t)row * 64 + tx * 4] = o;
        }
    }
}

// ---------------- 3a) partial mean-pool: 512 blocks x 64 threads ----------------
__global__ void pool_partial_kernel(const float* __restrict__ h) {
    const int b = blockIdx.x, c = blockIdx.y, k = threadIdx.x;
    const float* p = h + ((size_t)b * NN + c * 64) * HID + k;
    float s = 0.0f;
    #pragma unroll 16
    for (int i = 0; i < 64; i++) s += p[(size_t)i * HID];
    g_pool[(b * 16 + c) * HID + k] = s;
}

// ---------------- 3b) head: combine partials + MLP ----------------
__global__ void head_kernel(const float* __restrict__ Wf1,
                            const float* __restrict__ bf1,
                            const float* __restrict__ Wf2,
                            const float* __restrict__ bf2,
                            float* __restrict__ out) {
    const int b = blockIdx.x, tid = threadIdx.x;
    __shared__ float pooled[64];
    __shared__ float red[128];

    if (tid < 64) {
        float s = 0.0f;
        #pragma unroll
        for (int c = 0; c < 16; c++) s += g_pool[(b * 16 + c) * HID + tid];
        pooled[tid] = s * (1.0f / (float)NN);
    }
    __syncthreads();

    float a = bf1[tid];
    #pragma unroll
    for (int kk = 0; kk < 64; kk++) a = fmaf(pooled[kk], Wf1[kk * HEAD + tid], a);
    red[tid] = fmaxf(a, 0.0f) * Wf2[tid];
    __syncthreads();
    for (int off = 64; off > 0; off >>= 1) {
        if (tid < off) red[tid] += red[tid + off];
        __syncthreads();
    }
    if (tid == 0) out[b] = red[0] + bf2[0];
}

// ---------------- launch ----------------
extern "C" void kernel_launch(void* const* d_in, const int* in_sizes, int n_in,
                              void* d_out, int out_size) {
    const float* x   = (const float*)d_in[0];
    const float* adj = (const float*)d_in[1];
    const float* W1  = (const float*)d_in[2];
    const float* b1  = (const float*)d_in[3];
    const float* W2  = (const float*)d_in[4];
    const float* b2  = (const float*)d_in[5];
    const float* W3  = (const float*)d_in[6];
    const float* b3  = (const float*)d_in[7];
    const float* Wf1 = (const float*)d_in[8];
    const float* bf1 = (const float*)d_in[9];
    const float* Wf2 = (const float*)d_in[10];
    const float* bf2 = (const float*)d_in[11];
    float* out = (float*)d_out;

    float *h1, *h2;
    cudaGetSymbolAddress((void**)&h1, g_h1);
    cudaGetSymbolAddress((void**)&h2, g_h2);

    build_edges_kernel<<<TOTAL_NODES / 8, 256>>>(adj);
    gcn_layer_kernel<NDIM, true,  true ><<<TOTAL_NODES / 64, 256>>>(x,  W1, b1, h1);
    gcn_layer_kernel<HID,  false, true ><<<TOTAL_NODES / 64, 256>>>(h1, W2, b2, h2);
    gcn_layer_kernel<HID,  false, false><<<TOTAL_NODES / 64, 256>>>(h2, W3, b3, h1);
    dim3 pg(BATCH, 16);
    pool_partial_kernel<<<pg, 64>>>(h1);
    head_kernel<<<BATCH, 128>>>(Wf1, bf1, Wf2, bf2, out);
}